// round 5
// baseline (speedup 1.0000x reference)
#include <cuda_runtime.h>
#include <stdint.h>

#define Nn 4096
#define Cc 10
#define LMAX 128
#define S1 0.73105857863000489f      // sigmoid(1.0) in fp32
#define MB 32                        // k_mask blocks
#define MT 128                       // k_mask threads/block

// ---------------- scratch (static device globals; no allocation) ------------
__device__ int   g_colcnt[Nn];            // masked in-neighbor count of column k
__device__ int   g_colidx[Nn * LMAX];     // RANKS of masked in-neighbors of column k
__device__ int   g_deg[Nn];               // out-degree (masked rows only)
__device__ int   g_rowidx[Nn * LMAX];     // out-neighbor node ids (masked rows only)
__device__ unsigned char g_diag[Nn];
__device__ float g_mask[Nn];
__device__ int   g_rank[Nn];              // dense rank among masked nodes, -1 if unmasked
__device__ float g_wp[Nn];                // exp(-pos[p]) * m[p]
__device__ float g_Eq[Cc * Nn];           // exp(preds[q,i]) * m[q]
__device__ float g_Qs[Cc * Cc];           // sum_{q in class j, masked} exp(preds[q,i])
__device__ float g_T[Cc * Cc];            // correction part of pairwise sum
__device__ float g_Si[Cc * Cc];           // S_inter (masked)
__device__ float g_Sc[Cc * Cc];           // S_corr  (masked)
__device__ float g_Ncnt[Cc];
__device__ float g_Sdeg[Cc];
__device__ float g_W0[Cc];                // sum_{p in i, masked} wp*v0
__device__ float g_ce;
__device__ int   g_qn;                    // number of masked nodes
__device__ int   g_qlist[Nn];             // masked node ids by rank (deterministic order)
__device__ int   g_qlabel[Nn];            // their labels
// per-block partials (every slot overwritten every run -> no zeroing needed)
__device__ float g_Qpart[MB * Cc * Cc];
__device__ float g_Npart[MB * Cc];
__device__ float g_cepart[MB];
__device__ int   g_sync;                  // reset to 0 by the finishing block

// ---------------- fused per-node kernel --------------------------------------
// Zeroing + mask decode + CE + Eq/wp + class partials; the LAST block to finish
// reduces the partials, runs the rank prefix-scan, and resets g_sync.
__global__ void k_mask(const float* __restrict__ preds,
                       const int* __restrict__ labels,
                       const unsigned int* __restrict__ mask) {
    __shared__ float sQ[Cc * Cc];
    __shared__ float sN[Cc];
    __shared__ float scew[MT / 32];
    __shared__ int s_last;

    int tid = threadIdx.x;
    int b = blockIdx.x;
    int p = b * MT + tid;                  // exactly covers [0, Nn)

    if (tid < Cc * Cc) sQ[tid] = 0.f;
    if (tid < Cc) sN[tid] = 0.f;
    // zero structures consumed by later kernels (no same-kernel accumulation -> safe)
    g_colcnt[p] = 0; g_deg[p] = 0; g_diag[p] = 0;
    if (p < Cc * Cc) { g_T[p] = 0.f; g_Si[p] = 0.f; g_Sc[p] = 0.f; }
    if (p < Cc) { g_Sdeg[p] = 0.f; g_W0[p] = 0.f; }
    __syncthreads();

    float m = (mask[p] != 0u) ? 1.f : 0.f;   // 4-byte bool (i32 1 or f32 one-bits)
    g_mask[p] = m;

    float r[Cc], E[Cc];
    float se = 0.f;
#pragma unroll
    for (int c = 0; c < Cc; c++) {
        r[c] = preds[p * Cc + c];
        E[c] = __expf(r[c]);
        se += E[c];
    }
    int l = labels[p];
    float ce_c = __logf(se) - r[l];          // -log softmax[l]
    g_wp[p] = __fdividef(m, E[l]);           // exp(-r[l]) * m
#pragma unroll
    for (int i = 0; i < Cc; i++) {
        float e = E[i] * m;
        g_Eq[i * Nn + p] = e;
        if (m != 0.f) atomicAdd(&sQ[i * Cc + l], e);
    }
    if (m != 0.f) atomicAdd(&sN[l], 1.f);

    // warp-reduce ce, then per-warp slots
    int lane = tid & 31, wid = tid >> 5;
#pragma unroll
    for (int o = 16; o > 0; o >>= 1) ce_c += __shfl_down_sync(0xFFFFFFFFu, ce_c, o);
    if (lane == 0) scew[wid] = ce_c;
    __syncthreads();

    // publish per-block partials
    if (tid < Cc * Cc) g_Qpart[b * Cc * Cc + tid] = sQ[tid];
    if (tid < Cc) g_Npart[b * Cc + tid] = sN[tid];
    if (tid == 0) {
        float s = 0.f;
#pragma unroll
        for (int w = 0; w < MT / 32; w++) s += scew[w];
        g_cepart[b] = s;
    }
    __syncthreads();
    if (tid == 0) {
        __threadfence();
        s_last = (atomicAdd(&g_sync, 1) == MB - 1);
    }
    __syncthreads();
    if (!s_last) return;

    // ---- finale: this block sees all prior blocks' global writes ----
    __threadfence();

    // reduce partials (overwrite targets; no pre-zero needed)
    if (tid < Cc * Cc) {
        float s = 0.f;
#pragma unroll
        for (int k = 0; k < MB; k++) s += g_Qpart[k * Cc * Cc + tid];
        g_Qs[tid] = s;
    }
    if (tid < Cc) {
        float s = 0.f;
#pragma unroll
        for (int k = 0; k < MB; k++) s += g_Npart[k * Cc + tid];
        g_Ncnt[tid] = s;
    }
    if (tid == 0) {
        float s = 0.f;
#pragma unroll
        for (int k = 0; k < MB; k++) s += g_cepart[k];
        g_ce = s;
        g_sync = 0;                       // reset for next replay (deterministic)
    }

    // rank prefix scan: 128 threads x 32 contiguous nodes
    __shared__ int wsum[MT / 32];
    int base = tid * 32;
    unsigned int mv[32];
    int cnt = 0;
#pragma unroll
    for (int j = 0; j < 32; j++) {
        mv[j] = (__ldcg((const float*)&g_mask[base + j]) != 0.f);
        cnt += mv[j];
    }
    int inc = cnt;
#pragma unroll
    for (int o = 1; o < 32; o <<= 1) {
        int y = __shfl_up_sync(0xFFFFFFFFu, inc, o);
        if (lane >= o) inc += y;
    }
    if (lane == 31) wsum[wid] = inc;
    __syncthreads();
    int woff = 0;
#pragma unroll
    for (int k = 0; k < MT / 32; k++) if (k < wid) woff += wsum[k];
    int rk = woff + inc - cnt;             // exclusive prefix
#pragma unroll
    for (int j = 0; j < 32; j++) {
        int pp = base + j;
        if (mv[j]) {
            g_rank[pp] = rk;
            g_qlist[rk] = pp;
            g_qlabel[rk] = labels[pp];
            rk++;
        } else {
            g_rank[pp] = -1;
        }
    }
    if (tid == MT - 1) g_qn = rk;
}

// ---------------- build: one warp per masked row ------------------------------
// Reads ONLY masked rows (perfectly coalesced 16KB row segments); builds row
// lists (all out-neighbors) and column lists (ranks of masked in-neighbors).
__global__ void k_build(const unsigned int* __restrict__ adj) {
    int lane = threadIdx.x & 31;
    int wid = threadIdx.x >> 5;                       // 0..7
    int r = wid * gridDim.x + blockIdx.x;             // rank (balanced across blocks)
    if (r >= g_qn) return;
    int p = g_qlist[r];
    const uint4* rowp = (const uint4*)(adj + (size_t)p * Nn);   // 1024 uint4

#pragma unroll
    for (int it = 0; it < 4; it++) {
        uint4 a[8];
#pragma unroll
        for (int s = 0; s < 8; s++) a[s] = rowp[lane + (it * 8 + s) * 32];
#pragma unroll
        for (int s = 0; s < 8; s++) {
            if (a[s].x | a[s].y | a[s].z | a[s].w) {
                int i4 = lane + (it * 8 + s) * 32;
                unsigned parts[4] = {a[s].x, a[s].y, a[s].z, a[s].w};
#pragma unroll
                for (int u = 0; u < 4; u++) {
                    if (parts[u]) {
                        int kk = i4 * 4 + u;
                        int ri = atomicAdd(&g_deg[p], 1);
                        if (ri < LMAX) g_rowidx[p * LMAX + ri] = kk;
                        int ci = atomicAdd(&g_colcnt[kk], 1);
                        if (ci < LMAX) g_colidx[kk * LMAX + ci] = r;
                        if (p == kk) g_diag[p] = 1;
                    }
                }
            }
        }
    }
}

// ---------------- per-row pairwise kernel -------------------------------------
// One block per masked node p. Rank-compacted dense counter in SMEM: multiset
// expansion over out-neighbors' masked-in-neighbor rank lists gives inter[p,*];
// corr bit for out-neighbors lacking a self-loop.
__global__ void k_process() {
    int bi = blockIdx.x;
    int qn = g_qn;
    if (bi >= qn) return;
    __shared__ unsigned int scnt[Nn];
    __shared__ int s_nbr[LMAX];
    __shared__ float sT[Cc], sSi[Cc], sSc[Cc];

    int tid = threadIdx.x;
    int p = g_qlist[bi];
    int cp = g_qlabel[bi];

    for (int i = tid; i < qn; i += blockDim.x) scnt[i] = 0u;
    if (tid < Cc) { sT[tid] = 0.f; sSi[tid] = 0.f; sSc[tid] = 0.f; }

    int dp = min(g_deg[p], LMAX);
    for (int i = tid; i < dp; i += blockDim.x) s_nbr[i] = g_rowidx[p * LMAX + i];
    __syncthreads();

    int wid = tid >> 5, lane = tid & 31;
    for (int i = wid; i < dp; i += 8) {
        int k = s_nbr[i];
        int c = min(g_colcnt[k], LMAX);
        const int* cl = g_colidx + k * LMAX;
        for (int j = lane; j < c; j += 32) atomicAdd(&scnt[cl[j]], 1u);
    }
    for (int i = tid; i < dp; i += blockDim.x) {
        int q = s_nbr[i];
        int rq = g_rank[q];
        if (rq >= 0 && !g_diag[q]) atomicAdd(&scnt[rq], 65536u);
    }
    __syncthreads();

    float wp = g_wp[p];
    float degp = (float)g_deg[p];
    float v0 = 1.0f / (1.0f + __expf(1.0f + S1 * degp));   // 1 - sigmoid
    const float* eqrow = g_Eq + cp * Nn;

    for (int i = tid; i < qn; i += blockDim.x) {
        unsigned w = scnt[i];
        if (!w) continue;
        int lq = g_qlabel[i];
        if (lq == cp) continue;                 // same-class pairs never used
        float inter = (float)(w & 0xFFFFu);
        float corr  = (float)(w >> 16);
        float sub = degp - inter - corr;
        float arg = (1.0f + S1 * sub) / (1.0f + S1 * inter);
        float v = 1.0f / (1.0f + __expf(arg));  // 1 - sigmoid(arg)
        atomicAdd(&sT[lq], wp * eqrow[g_qlist[i]] * (v - v0));
        atomicAdd(&sSi[lq], inter);
        atomicAdd(&sSc[lq], corr);
    }
    __syncthreads();
    if (tid < Cc && tid != cp) {
        int idx = cp * Cc + tid;
        if (sT[tid]  != 0.f) atomicAdd(&g_T[idx],  sT[tid]);
        if (sSi[tid] != 0.f) atomicAdd(&g_Si[idx], sSi[tid]);
        if (sSc[tid] != 0.f) atomicAdd(&g_Sc[idx], sSc[tid]);
    }
    if (tid == 0) {
        atomicAdd(&g_Sdeg[cp], degp);
        atomicAdd(&g_W0[cp], wp * v0);
    }
}

__global__ void k_final(float* __restrict__ out) {
    if (threadIdx.x == 0 && blockIdx.x == 0) {
        float acc = 0.f;
        for (int i = 0; i < Cc; i++) {
            for (int j = 0; j < Cc; j++) {
                if (i == j) continue;
                int idx = i * Cc + j;
                float Si = g_Si[idx];
                float Ssub = g_Sdeg[i] * g_Ncnt[j] - Si - g_Sc[idx];  // exact ints in f32
                if (Si > 0.f && Ssub > 0.f) {
                    float T = g_T[idx] + g_W0[i] * g_Qs[idx];  // correction + base
                    float ni = fmaxf(g_Ncnt[i], 1.f);
                    float nj = fmaxf(g_Ncnt[j], 1.f);
                    acc += T / (ni * nj);
                }
            }
        }
        out[0] = g_ce / (float)Nn + 0.001f * acc;
    }
}

// ---------------- launch -----------------------------------------------------
extern "C" void kernel_launch(void* const* d_in, const int* in_sizes, int n_in,
                              void* d_out, int out_size) {
    const float* preds  = (const float*)d_in[0];
    const int*   labels = (const int*)d_in[1];
    const unsigned int* mask = (const unsigned int*)d_in[2];
    const unsigned int* adj  = (const unsigned int*)d_in[3];

    k_mask<<<MB, MT>>>(preds, labels, mask);
    k_build<<<512, 256>>>(adj);       // 8 warps/block; warp (w,b) -> rank w*512+b
    k_process<<<Nn, 256>>>();
    k_final<<<1, 32>>>((float*)d_out);
}

// round 6
// speedup vs baseline: 1.0204x; 1.0204x over previous
#include <cuda_runtime.h>
#include <stdint.h>

#define Nn 4096
#define Cc 10
#define LMAX 128
#define S1 0.73105857863000489f      // sigmoid(1.0) in fp32
#define MB 32                        // k_mask blocks
#define MT 128                       // k_mask threads/block

// ---------------- scratch (static device globals; no allocation) ------------
__device__ int   g_colcnt[Nn];            // masked in-neighbor count of column k
__device__ int   g_colidx[Nn * LMAX];     // RANKS of masked in-neighbors of column k
__device__ int   g_deg[Nn];               // out-degree (masked rows only)
__device__ int   g_rowidx[Nn * LMAX];     // out-neighbor node ids (masked rows only)
__device__ unsigned char g_diag[Nn];
__device__ float g_mask[Nn];
__device__ int   g_rank[Nn];              // dense rank among masked nodes, -1 if unmasked
__device__ float g_wp[Nn];                // exp(-pos[p]) * m[p]
__device__ float g_Eq[Cc * Nn];           // exp(preds[q,i]) * m[q]
__device__ float g_Qs[Cc * Cc];           // sum_{q in class j, masked} exp(preds[q,i])
__device__ float g_T[Cc * Cc];            // correction part of pairwise sum
__device__ float g_Si[Cc * Cc];           // S_inter (masked)
__device__ float g_Sc[Cc * Cc];           // S_corr  (masked)
__device__ float g_Ncnt[Cc];
__device__ float g_Sdeg[Cc];
__device__ float g_W0[Cc];                // sum_{p in i, masked} wp*v0
__device__ float g_ce;
__device__ int   g_qn;                    // number of masked nodes
__device__ int   g_qlist[Nn];             // masked node ids by rank (deterministic order)
__device__ int   g_qlabel[Nn];            // their labels
// per-block partials (every slot overwritten every run -> no zeroing needed)
__device__ float g_Qpart[MB * Cc * Cc];
__device__ float g_Npart[MB * Cc];
__device__ float g_cepart[MB];
__device__ int   g_sync;                  // k_mask arrival counter (self-resetting)
__device__ int   g_done;                  // k_process arrival counter (self-resetting)

// ---------------- fused per-node kernel --------------------------------------
// Zeroing + mask decode + CE + Eq/wp + class partials; the LAST block to finish
// reduces the partials, runs the rank prefix-scan, and resets g_sync.
__global__ void k_mask(const float* __restrict__ preds,
                       const int* __restrict__ labels,
                       const unsigned int* __restrict__ mask) {
    __shared__ float sQ[Cc * Cc];
    __shared__ float sN[Cc];
    __shared__ float scew[MT / 32];
    __shared__ int s_last;

    int tid = threadIdx.x;
    int b = blockIdx.x;
    int p = b * MT + tid;                  // exactly covers [0, Nn)

    if (tid < Cc * Cc) sQ[tid] = 0.f;
    if (tid < Cc) sN[tid] = 0.f;
    // zero structures consumed by later kernels (no same-kernel accumulation -> safe)
    g_colcnt[p] = 0; g_deg[p] = 0; g_diag[p] = 0;
    if (p < Cc * Cc) { g_T[p] = 0.f; g_Si[p] = 0.f; g_Sc[p] = 0.f; }
    if (p < Cc) { g_Sdeg[p] = 0.f; g_W0[p] = 0.f; }
    __syncthreads();

    float m = (mask[p] != 0u) ? 1.f : 0.f;   // 4-byte bool (i32 1 or f32 one-bits)
    g_mask[p] = m;

    float r[Cc], E[Cc];
    float se = 0.f;
#pragma unroll
    for (int c = 0; c < Cc; c++) {
        r[c] = preds[p * Cc + c];
        E[c] = __expf(r[c]);
        se += E[c];
    }
    int l = labels[p];
    float ce_c = __logf(se) - r[l];          // -log softmax[l]
    g_wp[p] = __fdividef(m, E[l]);           // exp(-r[l]) * m
#pragma unroll
    for (int i = 0; i < Cc; i++) {
        float e = E[i] * m;
        g_Eq[i * Nn + p] = e;
        if (m != 0.f) atomicAdd(&sQ[i * Cc + l], e);
    }
    if (m != 0.f) atomicAdd(&sN[l], 1.f);

    // warp-reduce ce, then per-warp slots
    int lane = tid & 31, wid = tid >> 5;
#pragma unroll
    for (int o = 16; o > 0; o >>= 1) ce_c += __shfl_down_sync(0xFFFFFFFFu, ce_c, o);
    if (lane == 0) scew[wid] = ce_c;
    __syncthreads();

    // publish per-block partials
    if (tid < Cc * Cc) g_Qpart[b * Cc * Cc + tid] = sQ[tid];
    if (tid < Cc) g_Npart[b * Cc + tid] = sN[tid];
    if (tid == 0) {
        float s = 0.f;
#pragma unroll
        for (int w = 0; w < MT / 32; w++) s += scew[w];
        g_cepart[b] = s;
    }
    __syncthreads();
    if (tid == 0) {
        __threadfence();
        s_last = (atomicAdd(&g_sync, 1) == MB - 1);
    }
    __syncthreads();
    if (!s_last) return;

    // ---- finale: this block sees all prior blocks' global writes ----
    __threadfence();

    if (tid < Cc * Cc) {
        float s = 0.f;
#pragma unroll
        for (int k = 0; k < MB; k++) s += g_Qpart[k * Cc * Cc + tid];
        g_Qs[tid] = s;
    }
    if (tid < Cc) {
        float s = 0.f;
#pragma unroll
        for (int k = 0; k < MB; k++) s += g_Npart[k * Cc + tid];
        g_Ncnt[tid] = s;
    }
    if (tid == 0) {
        float s = 0.f;
#pragma unroll
        for (int k = 0; k < MB; k++) s += g_cepart[k];
        g_ce = s;
        g_sync = 0;                       // reset for next replay (deterministic)
    }

    // rank prefix scan: 128 threads x 32 contiguous nodes
    __shared__ int wsum[MT / 32];
    int base = tid * 32;
    unsigned int mv[32];
    int cnt = 0;
#pragma unroll
    for (int j = 0; j < 32; j++) {
        mv[j] = (__ldcg((const float*)&g_mask[base + j]) != 0.f);
        cnt += mv[j];
    }
    int inc = cnt;
#pragma unroll
    for (int o = 1; o < 32; o <<= 1) {
        int y = __shfl_up_sync(0xFFFFFFFFu, inc, o);
        if (lane >= o) inc += y;
    }
    if (lane == 31) wsum[wid] = inc;
    __syncthreads();
    int woff = 0;
#pragma unroll
    for (int k = 0; k < MT / 32; k++) if (k < wid) woff += wsum[k];
    int rk = woff + inc - cnt;             // exclusive prefix
#pragma unroll
    for (int j = 0; j < 32; j++) {
        int pp = base + j;
        if (mv[j]) {
            g_rank[pp] = rk;
            g_qlist[rk] = pp;
            g_qlabel[rk] = labels[pp];
            rk++;
        } else {
            g_rank[pp] = -1;
        }
    }
    if (tid == MT - 1) g_qn = rk;
}

// ---------------- build: one warp per masked row ------------------------------
// Reads ONLY masked rows (perfectly coalesced 16KB row segments); builds row
// lists (all out-neighbors) and column lists (ranks of masked in-neighbors).
__global__ void k_build(const unsigned int* __restrict__ adj) {
    int lane = threadIdx.x & 31;
    int wid = threadIdx.x >> 5;                       // 0..7
    int r = wid * gridDim.x + blockIdx.x;             // rank (balanced across blocks)
    if (r >= g_qn) return;
    int p = g_qlist[r];
    const uint4* rowp = (const uint4*)(adj + (size_t)p * Nn);   // 1024 uint4

#pragma unroll
    for (int it = 0; it < 4; it++) {
        uint4 a[8];
#pragma unroll
        for (int s = 0; s < 8; s++) a[s] = rowp[lane + (it * 8 + s) * 32];
#pragma unroll
        for (int s = 0; s < 8; s++) {
            if (a[s].x | a[s].y | a[s].z | a[s].w) {
                int i4 = lane + (it * 8 + s) * 32;
                unsigned parts[4] = {a[s].x, a[s].y, a[s].z, a[s].w};
#pragma unroll
                for (int u = 0; u < 4; u++) {
                    if (parts[u]) {
                        int kk = i4 * 4 + u;
                        int ri = atomicAdd(&g_deg[p], 1);
                        if (ri < LMAX) g_rowidx[p * LMAX + ri] = kk;
                        int ci = atomicAdd(&g_colcnt[kk], 1);
                        if (ci < LMAX) g_colidx[kk * LMAX + ci] = r;
                        if (p == kk) g_diag[p] = 1;
                    }
                }
            }
        }
    }
}

// ---------------- per-row pairwise kernel + fused final reduction -------------
// One block per masked node p (grid = Nn; extra blocks just arrive). Rank-
// compacted dense counter in SMEM; multiset expansion over out-neighbors'
// masked-in-neighbor rank lists gives inter[p,*]; corr bit for out-neighbors
// lacking a self-loop. The LAST block to arrive computes the final loss with
// one thread per (i,j) class pair (all loads independent -> one round-trip).
__global__ void k_process(float* __restrict__ out) {
    __shared__ unsigned int scnt[Nn];
    __shared__ int s_nbr[LMAX];
    __shared__ float sT[Cc], sSi[Cc], sSc[Cc];
    __shared__ int s_last;

    int bi = blockIdx.x;
    int qn = g_qn;
    int tid = threadIdx.x;

    if (bi < qn) {
        int p = g_qlist[bi];
        int cp = g_qlabel[bi];

        for (int i = tid; i < qn; i += blockDim.x) scnt[i] = 0u;
        if (tid < Cc) { sT[tid] = 0.f; sSi[tid] = 0.f; sSc[tid] = 0.f; }

        int dp = min(g_deg[p], LMAX);
        for (int i = tid; i < dp; i += blockDim.x) s_nbr[i] = g_rowidx[p * LMAX + i];
        __syncthreads();

        int wid = tid >> 5, lane = tid & 31;
        for (int i = wid; i < dp; i += 8) {
            int k = s_nbr[i];
            int c = min(g_colcnt[k], LMAX);
            const int* cl = g_colidx + k * LMAX;
            for (int j = lane; j < c; j += 32) atomicAdd(&scnt[cl[j]], 1u);
        }
        for (int i = tid; i < dp; i += blockDim.x) {
            int q = s_nbr[i];
            int rq = g_rank[q];
            if (rq >= 0 && !g_diag[q]) atomicAdd(&scnt[rq], 65536u);
        }
        __syncthreads();

        float wp = g_wp[p];
        float degp = (float)g_deg[p];
        float v0 = 1.0f / (1.0f + __expf(1.0f + S1 * degp));   // 1 - sigmoid
        const float* eqrow = g_Eq + cp * Nn;

        for (int i = tid; i < qn; i += blockDim.x) {
            unsigned w = scnt[i];
            if (!w) continue;
            int lq = g_qlabel[i];
            if (lq == cp) continue;                 // same-class pairs never used
            float inter = (float)(w & 0xFFFFu);
            float corr  = (float)(w >> 16);
            float sub = degp - inter - corr;
            float arg = (1.0f + S1 * sub) / (1.0f + S1 * inter);
            float v = 1.0f / (1.0f + __expf(arg));  // 1 - sigmoid(arg)
            atomicAdd(&sT[lq], wp * eqrow[g_qlist[i]] * (v - v0));
            atomicAdd(&sSi[lq], inter);
            atomicAdd(&sSc[lq], corr);
        }
        __syncthreads();
        if (tid < Cc && tid != cp) {
            int idx = cp * Cc + tid;
            if (sT[tid]  != 0.f) atomicAdd(&g_T[idx],  sT[tid]);
            if (sSi[tid] != 0.f) atomicAdd(&g_Si[idx], sSi[tid]);
            if (sSc[tid] != 0.f) atomicAdd(&g_Sc[idx], sSc[tid]);
        }
        if (tid == 0) {
            atomicAdd(&g_Sdeg[cp], degp);
            atomicAdd(&g_W0[cp], wp * v0);
        }
    }

    // ---- arrival + fused final reduction in the last block ----
    __syncthreads();
    if (tid == 0) {
        __threadfence();
        s_last = (atomicAdd(&g_done, 1) == gridDim.x - 1);
    }
    __syncthreads();
    if (!s_last) return;
    __threadfence();

    // one thread per class pair; all loads issue independently
    float contrib = 0.f;
    if (tid < Cc * Cc) {
        int i = tid / Cc, j = tid - i * Cc;
        if (i != j) {
            float Si = g_Si[tid];
            float Ssub = g_Sdeg[i] * g_Ncnt[j] - Si - g_Sc[tid];  // exact ints in f32
            if (Si > 0.f && Ssub > 0.f) {
                float T = g_T[tid] + g_W0[i] * g_Qs[tid];  // correction + base
                float ni = fmaxf(g_Ncnt[i], 1.f);
                float nj = fmaxf(g_Ncnt[j], 1.f);
                contrib = T / (ni * nj);
            }
        }
    }
    // deterministic tree reduction over 128 threads via smem
    __shared__ float sred[128];
    sred[tid] = contrib;
    __syncthreads();
    for (int o = 64; o > 0; o >>= 1) {
        if (tid < o) sred[tid] += sred[tid + o];
        __syncthreads();
    }
    if (tid == 0) {
        out[0] = g_ce / (float)Nn + 0.001f * sred[0];
        g_done = 0;                          // reset for next replay
    }
}

// ---------------- launch -----------------------------------------------------
extern "C" void kernel_launch(void* const* d_in, const int* in_sizes, int n_in,
                              void* d_out, int out_size) {
    const float* preds  = (const float*)d_in[0];
    const int*   labels = (const int*)d_in[1];
    const unsigned int* mask = (const unsigned int*)d_in[2];
    const unsigned int* adj  = (const unsigned int*)d_in[3];

    k_mask<<<MB, MT>>>(preds, labels, mask);
    k_build<<<512, 256>>>(adj);       // 8 warps/block; warp (w,b) -> rank w*512+b
    k_process<<<Nn, 128>>>((float*)d_out);
}